// round 1
// baseline (speedup 1.0000x reference)
#include <cuda_runtime.h>
#include <math.h>

#define PI_C 3.14159f

// ---------------- scratch (allocation-free rule: __device__ globals) --------
__device__ float  g_p[8 * 256];       // hidden activations p = relu(pc@W1+b1)
__device__ float4 g_tf[8 * 256];      // per-(b,d): (cos*sc, sin*sc, tx, ty)

// ---------------- kernel 1: p = relu(para_code @ W1 + b1) -------------------
// grid: 8 blocks (one per batch row), 256 threads (one per output feature)
__global__ void mlp1_kernel(const float* __restrict__ pc,
                            const float* __restrict__ W1,
                            const float* __restrict__ b1) {
    __shared__ float spc[256];
    const int b = blockIdx.x;
    const int j = threadIdx.x;
    spc[j] = pc[b * 256 + j];
    __syncthreads();
    float acc = b1[j];
    #pragma unroll 8
    for (int k = 0; k < 256; ++k) {
        acc = fmaf(spc[k], W1[k * 256 + j], acc);
    }
    g_p[b * 256 + j] = fmaxf(acc, 0.0f);
}

// ---------------- kernel 2: per-(b,d) affine params -------------------------
// grid: 8 blocks, 256 threads (one per d)
__global__ void mlp2_kernel(const float* __restrict__ Ws, const float* __restrict__ bs,
                            const float* __restrict__ Wr, const float* __restrict__ br,
                            const float* __restrict__ Wt, const float* __restrict__ bt) {
    __shared__ float sp[256];
    const int b = blockIdx.x;
    const int d = threadIdx.x;
    sp[d] = g_p[b * 256 + d];
    __syncthreads();

    float acc_s = bs[d];
    float acc_r = br[d];
    float acc_t0 = bt[2 * d];
    float acc_t1 = bt[2 * d + 1];
    #pragma unroll 4
    for (int k = 0; k < 256; ++k) {
        const float pk = sp[k];
        acc_s  = fmaf(pk, Ws[k * 256 + d],     acc_s);
        acc_r  = fmaf(pk, Wr[k * 256 + d],     acc_r);
        acc_t0 = fmaf(pk, Wt[k * 512 + 2 * d],     acc_t0);
        acc_t1 = fmaf(pk, Wt[k * 512 + 2 * d + 1], acc_t1);
    }
    const float scale = 2.0f / (1.0f + expf(-acc_s));   // sigmoid * 2
    const float ang   = tanhf(acc_r) * PI_C;
    const float c = cosf(ang) * scale;
    const float s = sinf(ang) * scale;
    const float tx = tanhf(acc_t0);
    const float ty = tanhf(acc_t1);
    g_tf[b * 256 + d] = make_float4(c, s, tx, ty);
}

// ---------------- kernel 3: affine bilinear resample, SMEM-staged -----------
// grid: B*D = 2048 blocks, 512 threads, 64KB dynamic smem (one full image)
__global__ __launch_bounds__(512) void resample_kernel(
        const float* __restrict__ fm, float* __restrict__ out) {
    extern __shared__ float tile[];           // 128*128 = 16384 floats = 64KB
    const int n = blockIdx.x;
    const float* __restrict__ img = fm + (size_t)n * 16384;

    // coalesced float4 stage-in
    {
        const float4* __restrict__ i4 = (const float4*)img;
        float4* t4 = (float4*)tile;
        #pragma unroll
        for (int i = threadIdx.x; i < 4096; i += 512) t4[i] = i4[i];
    }

    // fold normalize->rotate/scale->translate->pixel-map into 3 consts/axis:
    //   gx = k*x - 1 (k = 2/127), new_x = a*gx - s*gy + tx
    //   px = new_x*64 + 63.5  (align_corners=False remap for W=128)
    const float4 tf = g_tf[n];
    const float a = tf.x, s = tf.y, tx = tf.z, ty = tf.w;
    const float k64 = 64.0f * (2.0f / 127.0f);
    const float Ax = a * k64,  Ay = -s * k64, A0 = (tx - a + s) * 64.0f + 63.5f;
    const float Bx = s * k64,  By =  a * k64, B0 = (ty - s - a) * 64.0f + 63.5f;

    __syncthreads();

    float* __restrict__ o = out + (size_t)n * 16384;
    #pragma unroll 4
    for (int idx = threadIdx.x; idx < 16384; idx += 512) {
        const float x = (float)(idx & 127);
        const float y = (float)(idx >> 7);
        float px = fmaf(Ax, x, fmaf(Ay, y, A0));
        float py = fmaf(Bx, x, fmaf(By, y, B0));
        px = fminf(fmaxf(px, 0.0f), 127.0f);   // padding_mode='border'
        py = fminf(fmaxf(py, 0.0f), 127.0f);
        const float x0f = floorf(px);
        const float y0f = floorf(py);
        const float wx = px - x0f;
        const float wy = py - y0f;
        const int x0 = (int)x0f;
        const int y0 = (int)y0f;
        const int x1 = min(x0 + 1, 127);
        const int y1 = min(y0 + 1, 127);
        const int r0 = y0 << 7;
        const int r1 = y1 << 7;
        const float v00 = tile[r0 + x0];
        const float v01 = tile[r0 + x1];
        const float v10 = tile[r1 + x0];
        const float v11 = tile[r1 + x1];
        const float top = fmaf(wx, v01 - v00, v00);
        const float bot = fmaf(wx, v11 - v10, v10);
        o[idx] = fmaf(wy, bot - top, top);
    }
}

// ---------------- launch -----------------------------------------------------
extern "C" void kernel_launch(void* const* d_in, const int* in_sizes, int n_in,
                              void* d_out, int out_size) {
    const float* feature_map = (const float*)d_in[0];   // (8,256,128,128)
    const float* para_code   = (const float*)d_in[1];   // (8,256)
    const float* W1 = (const float*)d_in[2];            // (256,256)
    const float* b1 = (const float*)d_in[3];            // (256,)
    const float* Ws = (const float*)d_in[4];            // (256,256)
    const float* bs = (const float*)d_in[5];            // (256,)
    const float* Wr = (const float*)d_in[6];            // (256,256)
    const float* br = (const float*)d_in[7];            // (256,)
    const float* Wt = (const float*)d_in[8];            // (256,512)
    const float* bt = (const float*)d_in[9];            // (512,)
    float* out = (float*)d_out;

    // 64KB dynamic smem opt-in (idempotent host-side attribute, not a stream op)
    cudaFuncSetAttribute(resample_kernel,
                         cudaFuncAttributeMaxDynamicSharedMemorySize, 65536);

    mlp1_kernel<<<8, 256>>>(para_code, W1, b1);
    mlp2_kernel<<<8, 256>>>(Ws, bs, Wr, br, Wt, bt);
    resample_kernel<<<2048, 512, 65536>>>(feature_map, out);
}

// round 3
// speedup vs baseline: 1.9997x; 1.9997x over previous
#include <cuda_runtime.h>
#include <math.h>

#define PI_C 3.14159f
#define TILE_PITCH 129                     // odd pitch kills stride-128 bank conflicts
#define TILE_BYTES (128 * TILE_PITCH * 4)  // 66048

// ---------------- scratch (allocation-free rule: __device__ globals) --------
__device__ float g_p[8 * 256];       // hidden activations p = relu(pc@W1+b1)
__device__ float g_raw[4 * 8 * 256]; // raw pre-activation [f][b*256+d], f in {s,r,t0,t1}

// ---------------- kernel 1: p = relu(para_code @ W1 + b1) -------------------
// grid: 8 blocks (32 j-columns each), 256 threads = 32 jl x 8 k-splits.
// All 8 batches kept in registers -> W1 streamed once, 8 indep FMA chains.
__global__ void mlp1_kernel(const float* __restrict__ pc,
                            const float* __restrict__ W1,
                            const float* __restrict__ b1) {
    __shared__ float spc[8 * 256];          // all batches' para_code (8KB)
    __shared__ float part[8 * 8 * 32];      // [ks][b][jl] partials (8KB)
    const int tid = threadIdx.x;
    const int jl = tid & 31;
    const int ks = tid >> 5;                // 8 groups of 32 k
    const int j = blockIdx.x * 32 + jl;

    #pragma unroll
    for (int i = tid; i < 2048; i += 256) spc[i] = pc[i];
    __syncthreads();

    float acc[8];
    #pragma unroll
    for (int b = 0; b < 8; ++b) acc[b] = 0.0f;

    const int k0 = ks * 32;
    #pragma unroll 4
    for (int kk = 0; kk < 32; ++kk) {
        const int k = k0 + kk;
        const float w = W1[k * 256 + j];
        #pragma unroll
        for (int b = 0; b < 8; ++b) acc[b] = fmaf(spc[b * 256 + k], w, acc[b]);
    }
    #pragma unroll
    for (int b = 0; b < 8; ++b) part[(ks * 8 + b) * 32 + jl] = acc[b];
    __syncthreads();

    // 256 outputs per block: (b2, jl2) one per thread
    const int jl2 = tid & 31;
    const int b2 = tid >> 5;
    float sum = b1[blockIdx.x * 32 + jl2];
    #pragma unroll
    for (int k2 = 0; k2 < 8; ++k2) sum += part[(k2 * 8 + b2) * 32 + jl2];
    g_p[b2 * 256 + blockIdx.x * 32 + jl2] = fmaxf(sum, 0.0f);
}

// ---------------- kernel 2: raw affine params (pure GEMM, 4 families) -------
// grid: (8 dc, 4 f), 256 threads = 32 dl x 8 k-splits, 8 batches in registers.
__global__ void mlp2_kernel(const float* __restrict__ Ws, const float* __restrict__ bs,
                            const float* __restrict__ Wr, const float* __restrict__ br,
                            const float* __restrict__ Wt, const float* __restrict__ bt) {
    __shared__ float sp[8 * 256];
    __shared__ float part[8 * 8 * 32];
    const int tid = threadIdx.x;
    const int dl = tid & 31;
    const int ks = tid >> 5;
    const int f = blockIdx.y;
    const int d = blockIdx.x * 32 + dl;

    #pragma unroll
    for (int i = tid; i < 2048; i += 256) sp[i] = g_p[i];
    __syncthreads();

    const float* __restrict__ Wcol;
    int stride;
    if (f == 0)      { Wcol = Ws + d;          stride = 256; }
    else if (f == 1) { Wcol = Wr + d;          stride = 256; }
    else if (f == 2) { Wcol = Wt + 2 * d;      stride = 512; }
    else             { Wcol = Wt + 2 * d + 1;  stride = 512; }

    float acc[8];
    #pragma unroll
    for (int b = 0; b < 8; ++b) acc[b] = 0.0f;

    const int k0 = ks * 32;
    #pragma unroll 4
    for (int kk = 0; kk < 32; ++kk) {
        const int k = k0 + kk;
        const float w = Wcol[(size_t)k * stride];
        #pragma unroll
        for (int b = 0; b < 8; ++b) acc[b] = fmaf(sp[b * 256 + k], w, acc[b]);
    }
    #pragma unroll
    for (int b = 0; b < 8; ++b) part[(ks * 8 + b) * 32 + dl] = acc[b];
    __syncthreads();

    const int dl2 = tid & 31;
    const int b2 = tid >> 5;
    const int d2 = blockIdx.x * 32 + dl2;
    float bias;
    if (f == 0)      bias = bs[d2];
    else if (f == 1) bias = br[d2];
    else if (f == 2) bias = bt[2 * d2];
    else             bias = bt[2 * d2 + 1];
    float sum = bias;
    #pragma unroll
    for (int k2 = 0; k2 < 8; ++k2) sum += part[(k2 * 8 + b2) * 32 + dl2];
    g_raw[f * 2048 + b2 * 256 + d2] = sum;
}

// ---------------- kernel 3: affine bilinear resample, pitched SMEM ----------
// grid: B*D = 2048 blocks, 512 threads, 66048B dynamic smem
__global__ __launch_bounds__(512) void resample_kernel(
        const float* __restrict__ fm, float* __restrict__ out) {
    extern __shared__ float tile[];           // 128 rows x 129 pitch
    __shared__ float s_cf[6];                 // Ax, Ay, A0, Bx, By, B0
    const int n = blockIdx.x;
    const int tid = threadIdx.x;
    const float* __restrict__ img = fm + (size_t)n * 16384;

    if (tid == 0) {
        const float raw_s = g_raw[n];
        const float raw_r = g_raw[2048 + n];
        const float raw_t0 = g_raw[2 * 2048 + n];
        const float raw_t1 = g_raw[3 * 2048 + n];
        const float scale = 2.0f / (1.0f + expf(-raw_s));
        const float ang = tanhf(raw_r) * PI_C;
        const float a = cosf(ang) * scale;
        const float s = sinf(ang) * scale;
        const float tx = tanhf(raw_t0);
        const float ty = tanhf(raw_t1);
        const float k64 = 64.0f * (2.0f / 127.0f);
        s_cf[0] = a * k64;                        // Ax
        s_cf[1] = -s * k64;                       // Ay
        s_cf[2] = (tx - a + s) * 64.0f + 63.5f;   // A0
        s_cf[3] = s * k64;                        // Bx
        s_cf[4] = a * k64;                        // By
        s_cf[5] = (ty - s - a) * 64.0f + 63.5f;   // B0
    }

    // coalesced float4 read from GMEM, pitched scalar stores to SMEM
    {
        const float4* __restrict__ i4 = (const float4*)img;
        #pragma unroll
        for (int i = tid; i < 4096; i += 512) {
            const float4 v = i4[i];
            const int x = (i & 31) * 4;
            const int y = i >> 5;
            float* dst = &tile[y * TILE_PITCH + x];
            dst[0] = v.x; dst[1] = v.y; dst[2] = v.z; dst[3] = v.w;
        }
    }
    __syncthreads();

    const float Ax = s_cf[0], Ay = s_cf[1], A0 = s_cf[2];
    const float Bx = s_cf[3], By = s_cf[4], B0 = s_cf[5];

    float* __restrict__ o = out + (size_t)n * 16384;
    #pragma unroll 4
    for (int idx = tid; idx < 16384; idx += 512) {
        const float x = (float)(idx & 127);
        const float y = (float)(idx >> 7);
        float px = fmaf(Ax, x, fmaf(Ay, y, A0));
        float py = fmaf(Bx, x, fmaf(By, y, B0));
        px = fminf(fmaxf(px, 0.0f), 127.0f);   // padding_mode='border'
        py = fminf(fmaxf(py, 0.0f), 127.0f);
        const float x0f = floorf(px);
        const float y0f = floorf(py);
        const float wx = px - x0f;
        const float wy = py - y0f;
        const int x0 = (int)x0f;
        const int y0 = (int)y0f;
        const int x1 = min(x0 + 1, 127);
        const int y1 = min(y0 + 1, 127);
        const int r0 = y0 * TILE_PITCH;
        const int r1 = y1 * TILE_PITCH;
        const float v00 = tile[r0 + x0];
        const float v01 = tile[r0 + x1];
        const float v10 = tile[r1 + x0];
        const float v11 = tile[r1 + x1];
        const float top = fmaf(wx, v01 - v00, v00);
        const float bot = fmaf(wx, v11 - v10, v10);
        o[idx] = fmaf(wy, bot - top, top);
    }
}

// ---------------- launch -----------------------------------------------------
extern "C" void kernel_launch(void* const* d_in, const int* in_sizes, int n_in,
                              void* d_out, int out_size) {
    const float* feature_map = (const float*)d_in[0];   // (8,256,128,128)
    const float* para_code   = (const float*)d_in[1];   // (8,256)
    const float* W1 = (const float*)d_in[2];            // (256,256)
    const float* b1 = (const float*)d_in[3];            // (256,)
    const float* Ws = (const float*)d_in[4];            // (256,256)
    const float* bs = (const float*)d_in[5];            // (256,)
    const float* Wr = (const float*)d_in[6];            // (256,256)
    const float* br = (const float*)d_in[7];            // (256,)
    const float* Wt = (const float*)d_in[8];            // (256,512)
    const float* bt = (const float*)d_in[9];            // (512,)
    float* out = (float*)d_out;

    cudaFuncSetAttribute(resample_kernel,
                         cudaFuncAttributeMaxDynamicSharedMemorySize, TILE_BYTES);

    mlp1_kernel<<<8, 256>>>(para_code, W1, b1);
    mlp2_kernel<<<dim3(8, 4), 256>>>(Ws, bs, Wr, br, Wt, bt);
    resample_kernel<<<2048, 512, TILE_BYTES>>>(feature_map, out);
}